// round 1
// baseline (speedup 1.0000x reference)
#include <cuda_runtime.h>
#include <cuda_bf16.h>

// Problem constants (fixed by the reference)
#define NROWS 131072
#define KOFF  27
#define CH    64
#define TILE_R 64
#define GPAD   68   // padded row stride for gathered tile (multiple of 4, avoids conflicts)
#define THREADS 256

// Intermediate activation h = relu(conv1(feat))  — device global scratch (no allocs)
__device__ float g_h[(size_t)NROWS * CH];

// One k-offset-looped gather-GEMM:
//   out[row][o] = relu( sum_k sum_c src[nbr[row][k]][c] * W[k][c][o] + bias[o] (+ resid[row][o]) )
// Block: 64 rows x 64 outs. 256 threads, each computes a 4x4 register tile.
template <bool ADD_RESID>
__global__ __launch_bounds__(THREADS)
void sparse_conv_kernel(const float* __restrict__ src,
                        const float* __restrict__ W,
                        const float* __restrict__ bias,
                        const int*   __restrict__ nbr,
                        const float* __restrict__ resid,
                        float*       __restrict__ out)
{
    __shared__ float G[TILE_R][GPAD];      // gathered features, 64 x 68 floats
    __shared__ float Ws[CH][CH];           // W[k], 64 x 64
    __shared__ int   nbrS[TILE_R][KOFF];   // neighbor indices for this row tile

    const int t    = threadIdx.x;
    const int row0 = blockIdx.x * TILE_R;

    // Stage the neighbor tile once (64 rows x 27 = 1728 ints)
    for (int i = t; i < TILE_R * KOFF; i += THREADS) {
        int r = i / KOFF;
        int k = i - r * KOFF;
        nbrS[r][k] = nbr[(size_t)(row0 + r) * KOFF + k];
    }

    const int tx = t & 15;   // output-channel group: o in [tx*4, tx*4+4)
    const int ty = t >> 4;   // row group: rows ty*4 .. ty*4+3

    float acc[4][4] = {};

    for (int k = 0; k < KOFF; ++k) {
        __syncthreads();  // also covers nbrS staging on k==0

        // Load W[k] (16 KB) into smem: 1024 float4, 4 per thread
        {
            const float4* Wk  = reinterpret_cast<const float4*>(W + (size_t)k * CH * CH);
            float4*       WsV = reinterpret_cast<float4*>(&Ws[0][0]);
            #pragma unroll
            for (int j = 0; j < 4; ++j)
                WsV[t + THREADS * j] = Wk[t + THREADS * j];
        }

        // Gather 64 rows x 64 floats (1024 float4), 4 per thread. Coalesced
        // 16-float4 bursts per source row; source rows are L2-resident.
        #pragma unroll
        for (int j = 0; j < 4; ++j) {
            int item = t + THREADS * j;      // 0..1023
            int r    = item >> 4;            // row within tile
            int v    = item & 15;            // float4 slot within row
            int srcRow = nbrS[r][k];
            float4 f = reinterpret_cast<const float4*>(src + (size_t)srcRow * CH)[v];
            *reinterpret_cast<float4*>(&G[r][v * 4]) = f;
        }

        __syncthreads();

        // 64x64x64 smem GEMM fragment: per c, 1 LDS.128 + 4 LDS.32 + 16 FFMA
        #pragma unroll
        for (int c = 0; c < CH; ++c) {
            float4 wv = *reinterpret_cast<const float4*>(&Ws[c][tx * 4]);
            #pragma unroll
            for (int j = 0; j < 4; ++j) {
                float g = G[ty * 4 + j][c];
                acc[j][0] += g * wv.x;
                acc[j][1] += g * wv.y;
                acc[j][2] += g * wv.z;
                acc[j][3] += g * wv.w;
            }
        }
    }

    // Epilogue: bias, optional residual, ReLU
    #pragma unroll
    for (int j = 0; j < 4; ++j) {
        const size_t row = (size_t)(row0 + ty * 4 + j);
        #pragma unroll
        for (int q = 0; q < 4; ++q) {
            const int o = tx * 4 + q;
            float v = acc[j][q] + __ldg(&bias[o]);
            if (ADD_RESID) v += resid[row * CH + o];
            out[row * CH + o] = fmaxf(v, 0.0f);
        }
    }
}

extern "C" void kernel_launch(void* const* d_in, const int* in_sizes, int n_in,
                              void* d_out, int out_size)
{
    // metadata order: feat, W1, b1, W2, b2, nbr
    const float* feat = (const float*)d_in[0];
    const float* W1   = (const float*)d_in[1];
    const float* b1   = (const float*)d_in[2];
    const float* W2   = (const float*)d_in[3];
    const float* b2   = (const float*)d_in[4];
    const int*   nbr  = (const int*)  d_in[5];
    float* out = (float*)d_out;

    float* h = nullptr;
    cudaGetSymbolAddress((void**)&h, g_h);

    const int grid = NROWS / TILE_R;  // 2048

    // h = relu(conv1(feat))
    sparse_conv_kernel<false><<<grid, THREADS>>>(feat, W1, b1, nbr, nullptr, h);
    // out = relu(feat + conv2(h))
    sparse_conv_kernel<true ><<<grid, THREADS>>>(h,    W2, b2, nbr, feat,    out);
}

// round 4
// speedup vs baseline: 2.1376x; 2.1376x over previous
#include <cuda_runtime.h>
#include <cuda_bf16.h>
#include <cstdint>

#define NROWS 131072
#define KOFF  27
#define CH    64
#define TILE_M 128
#define THREADS 256
#define CONV_GRID (NROWS / TILE_M)

// ---------------- device global scratch (no allocs allowed) ----------------
__device__ __align__(16) float         g_h[(size_t)NROWS * CH];           // relu(conv1) fp32
__device__ __align__(16) __nv_bfloat16 g_Wt_hi[2][KOFF * CH * CH];        // [k][o][c] transposed
__device__ __align__(16) __nv_bfloat16 g_Wt_lo[2][KOFF * CH * CH];

// ---------------- helpers ----------------
__device__ __forceinline__ uint32_t smem_u32(const void* p) {
    uint32_t a;
    asm("{ .reg .u64 t; cvta.to.shared.u64 t, %1; cvt.u32.u64 %0, t; }" : "=r"(a) : "l"(p));
    return a;
}
__device__ __forceinline__ void ldsm_x4(uint32_t* r, uint32_t addr) {
    asm volatile("ldmatrix.sync.aligned.m8n8.x4.shared.b16 {%0,%1,%2,%3}, [%4];"
                 : "=r"(r[0]), "=r"(r[1]), "=r"(r[2]), "=r"(r[3]) : "r"(addr));
}
__device__ __forceinline__ void ldsm_x2(uint32_t* r, uint32_t addr) {
    asm volatile("ldmatrix.sync.aligned.m8n8.x2.shared.b16 {%0,%1}, [%2];"
                 : "=r"(r[0]), "=r"(r[1]) : "r"(addr));
}
__device__ __forceinline__ void mma16816(float* c, const uint32_t* a, const uint32_t* b) {
    asm volatile(
        "mma.sync.aligned.m16n8k16.row.col.f32.bf16.bf16.f32 "
        "{%0,%1,%2,%3}, {%4,%5,%6,%7}, {%8,%9}, {%0,%1,%2,%3};"
        : "+f"(c[0]), "+f"(c[1]), "+f"(c[2]), "+f"(c[3])
        : "r"(a[0]), "r"(a[1]), "r"(a[2]), "r"(a[3]), "r"(b[0]), "r"(b[1]));
}
__device__ __forceinline__ void sts128(uint32_t addr, uint4 v) {
    asm volatile("st.shared.v4.b32 [%0], {%1,%2,%3,%4};"
                 :: "r"(addr), "r"(v.x), "r"(v.y), "r"(v.z), "r"(v.w) : "memory");
}
__device__ __forceinline__ void sts64(uint32_t addr, uint2 v) {
    asm volatile("st.shared.v2.b32 [%0], {%1,%2};" :: "r"(addr), "r"(v.x), "r"(v.y) : "memory");
}

// ---------------- W prepass: transpose + hi/lo split ----------------
__global__ void convert_w_kernel(const float* __restrict__ W1, const float* __restrict__ W2) {
    int idx = blockIdx.x * blockDim.x + threadIdx.x;
    const int per = KOFF * CH * CH;
    if (idx >= 2 * per) return;
    int sel = idx / per;
    int r = idx - sel * per;          // r = k*4096 + o*64 + c
    int k = r / (CH * CH);
    int rem = r - k * (CH * CH);
    int o = rem / CH;
    int c = rem - o * CH;
    const float* W = sel ? W2 : W1;
    float v = W[k * CH * CH + c * CH + o];
    __nv_bfloat16 hb = __float2bfloat16(v);
    g_Wt_hi[sel][r] = hb;
    g_Wt_lo[sel][r] = __float2bfloat16(v - __bfloat162float(hb));
}

// ---------------- main conv: gather fp32 -> split bf16 -> mma.sync ----------------
// Static smem = exactly 48 KB (no opt-in, no dynamic smem, no attribute calls):
//   A_hi 128x64 bf16 (16KB), A_lo (16KB), B_hi 64x64 bf16 (8KB), B_lo (8KB).
// All tiles: rows of 128B (64 bf16); 16B chunks swizzled with (chunk ^ (row&7)).
template<bool FIRST>
__global__ __launch_bounds__(THREADS)
void conv_mma_kernel(const float* __restrict__ src,
                     const float* __restrict__ bias,
                     const int*   __restrict__ nbr,
                     const float* __restrict__ resid,
                     float*       __restrict__ outF)
{
    __shared__ __align__(128) __nv_bfloat16 sAhi[TILE_M * CH];
    __shared__ __align__(128) __nv_bfloat16 sAlo[TILE_M * CH];
    __shared__ __align__(128) __nv_bfloat16 sBhi[CH * CH];
    __shared__ __align__(128) __nv_bfloat16 sBlo[CH * CH];

    const uint32_t A_HI = smem_u32(sAhi), A_LO = smem_u32(sAlo);
    const uint32_t B_HI = smem_u32(sBhi), B_LO = smem_u32(sBlo);

    const int t   = threadIdx.x;
    const int w   = t >> 5;          // warp 0..7, rows [w*16, w*16+16)
    const int l   = t & 31;
    const int row0 = blockIdx.x * TILE_M;

    const __nv_bfloat16* __restrict__ wHi = g_Wt_hi[FIRST ? 0 : 1];
    const __nv_bfloat16* __restrict__ wLo = g_Wt_lo[FIRST ? 0 : 1];

    // ldmatrix lane-address components (constant across k)
    const int lr  = l & 7;
    const int sub = l >> 3;                 // 0..3  (A x4 submatrix id)
    const int hb  = (l >> 3) & 1;           // B x2 submatrix id
    const uint32_t rowA128 = (uint32_t)((w * 16 + (sub & 1) * 8 + lr) * 128);
    const uint32_t rowBbase = (uint32_t)(lr * 128);   // + nt*8*128

    float acc[8][4];
#pragma unroll
    for (int nt = 0; nt < 8; ++nt)
#pragma unroll
        for (int q = 0; q < 4; ++q) acc[nt][q] = 0.0f;

    for (int k = 0; k < KOFF; ++k) {
        __syncthreads();   // compute(k-1) done before smem overwrite

        // --- stage W[k] hi/lo: 2 x 512 16B chunks ---
#pragma unroll
        for (int jj = 0; jj < 4; ++jj) {
            int i   = t + THREADS * jj;        // 0..1023
            int sel = i >> 9;                  // 0: hi, 1: lo
            int c   = i & 511;
            int r   = c >> 3, p = c & 7;
            const __nv_bfloat16* wp = (sel ? wLo : wHi) + (size_t)k * (CH * CH) + r * 64 + p * 8;
            uint4 v = *reinterpret_cast<const uint4*>(wp);
            sts128((sel ? B_LO : B_HI) + (uint32_t)(r * 128 + ((p ^ (r & 7)) * 16)), v);
        }

        // --- gather A: 128 rows x 64 fp32 (2048 float4), split to bf16 hi/lo ---
#pragma unroll
        for (int jj = 0; jj < 8; ++jj) {
            int item = t + THREADS * jj;       // 0..2047
            int r = item >> 4;                 // row in tile
            int v = item & 15;                 // float4 slot (4 floats)
            int srow = __ldg(nbr + (size_t)(row0 + r) * KOFF + k);
            float4 f = reinterpret_cast<const float4*>(src + (size_t)srow * CH)[v];
            union { __nv_bfloat16 b[4]; uint2 u; } uh, ul;
            float x[4] = {f.x, f.y, f.z, f.w};
#pragma unroll
            for (int q = 0; q < 4; ++q) {
                __nv_bfloat16 hbv = __float2bfloat16(x[q]);
                uh.b[q] = hbv;
                ul.b[q] = __float2bfloat16(x[q] - __bfloat162float(hbv));
            }
            // byte col = v*8; chunk = v>>1, 8B offset = (v&1)*8
            uint32_t soff = (uint32_t)(r * 128 + (((v >> 1) ^ (r & 7)) * 16) + (v & 1) * 8);
            sts64(A_HI + soff, uh.u);
            sts64(A_LO + soff, ul.u);
        }

        __syncthreads();

        // --- compute: 4 ksteps x 8 n-tiles x 3 passes ---
#pragma unroll
        for (int ks = 0; ks < 4; ++ks) {
            uint32_t ah[4], al[4];
            uint32_t achunk = (uint32_t)(((ks * 2 + (sub >> 1)) ^ lr) * 16);
            ldsm_x4(ah, A_HI + rowA128 + achunk);
            ldsm_x4(al, A_LO + rowA128 + achunk);
            uint32_t bchunk = (uint32_t)(((ks * 2 + hb) ^ lr) * 16);
#pragma unroll
            for (int nt = 0; nt < 8; ++nt) {
                uint32_t bhr[2], blr[2];
                uint32_t boff = rowBbase + (uint32_t)(nt * 8 * 128) + bchunk;
                ldsm_x2(bhr, B_HI + boff);
                ldsm_x2(blr, B_LO + boff);
                mma16816(acc[nt], ah, bhr);
                mma16816(acc[nt], ah, blr);
                mma16816(acc[nt], al, bhr);
            }
        }
    }

    // ---------------- epilogue ----------------
    const int g  = l >> 2;
    const int tq = l & 3;
    const int rowA = row0 + w * 16 + g;
    const int rowB = rowA + 8;
#pragma unroll
    for (int nt = 0; nt < 8; ++nt) {
        const int n = nt * 8 + tq * 2;
        const float b0 = __ldg(bias + n), b1 = __ldg(bias + n + 1);
        if (FIRST) {
            float2 va, vb;
            va.x = fmaxf(acc[nt][0] + b0, 0.0f);
            va.y = fmaxf(acc[nt][1] + b1, 0.0f);
            vb.x = fmaxf(acc[nt][2] + b0, 0.0f);
            vb.y = fmaxf(acc[nt][3] + b1, 0.0f);
            *reinterpret_cast<float2*>(g_h + (size_t)rowA * CH + n) = va;
            *reinterpret_cast<float2*>(g_h + (size_t)rowB * CH + n) = vb;
        } else {
            float2 ra = *reinterpret_cast<const float2*>(resid + (size_t)rowA * CH + n);
            float2 rb = *reinterpret_cast<const float2*>(resid + (size_t)rowB * CH + n);
            float2 va, vb;
            va.x = fmaxf(acc[nt][0] + b0 + ra.x, 0.0f);
            va.y = fmaxf(acc[nt][1] + b1 + ra.y, 0.0f);
            vb.x = fmaxf(acc[nt][2] + b0 + rb.x, 0.0f);
            vb.y = fmaxf(acc[nt][3] + b1 + rb.y, 0.0f);
            *reinterpret_cast<float2*>(outF + (size_t)rowA * CH + n) = va;
            *reinterpret_cast<float2*>(outF + (size_t)rowB * CH + n) = vb;
        }
    }
}

// ---------------- launch ----------------
extern "C" void kernel_launch(void* const* d_in, const int* in_sizes, int n_in,
                              void* d_out, int out_size)
{
    const float* feat = (const float*)d_in[0];
    const float* W1   = (const float*)d_in[1];
    const float* b1   = (const float*)d_in[2];
    const float* W2   = (const float*)d_in[3];
    const float* b2   = (const float*)d_in[4];
    const int*   nbr  = (const int*)  d_in[5];
    float* out = (float*)d_out;

    float* h = nullptr;
    cudaGetSymbolAddress((void**)&h, g_h);

    convert_w_kernel<<<(2 * KOFF * CH * CH + 255) / 256, 256>>>(W1, W2);

    conv_mma_kernel<true ><<<CONV_GRID, THREADS>>>(feat, b1, nbr, nullptr, nullptr);
    conv_mma_kernel<false><<<CONV_GRID, THREADS>>>(h,    b2, nbr, feat,    out);
}